// round 2
// baseline (speedup 1.0000x reference)
#include <cuda_runtime.h>
#include <math.h>
#include <stdint.h>

#define BATCH 4
#define SEQ   4096
#define DIM   128

#define NEG_INF __int_as_float(0xff800000)

// Scratch (allocation-free: __device__ globals)
__device__ float g_key[(size_t)BATCH * SEQ * DIM];
__device__ float g_val[(size_t)BATCH * SEQ * DIM];
// Fallback attn/score buffer in case d_out only holds `out` (tuple not concatenated)
__device__ float g_attn_fb[(size_t)BATCH * SEQ * SEQ];

// ---------------------------------------------------------------------------
// Projection: out[m,e] = sum_d inp[m,d] * w[e,d]   (A * B^T), M=16384, N=K=128
// Tile: 128x128 per CTA, BK=16, 256 threads, 8x8 microtile.
// ---------------------------------------------------------------------------
__global__ void __launch_bounds__(256) proj_kernel(const float* __restrict__ inp,
                                                   const float* __restrict__ w,
                                                   int which) {
    float* outp = which ? g_val : g_key;
    __shared__ float As[16][128];
    __shared__ float Bs[16][128];

    const int tid   = threadIdx.x;
    const int mbase = blockIdx.x * 128;
    const int tm    = tid >> 4;   // 0..15 -> m = tm*8
    const int tn    = tid & 15;   // 0..15 -> n = tn*8

    float acc[8][8];
#pragma unroll
    for (int i = 0; i < 8; i++)
#pragma unroll
        for (int j = 0; j < 8; j++) acc[i][j] = 0.f;

    const int lr  = tid >> 2;  // 0..63
    const int lc4 = tid & 3;   // 0..3

    for (int k0 = 0; k0 < DIM; k0 += 16) {
#pragma unroll
        for (int it = 0; it < 2; ++it) {
            int row = lr + it * 64;
            float4 a = *reinterpret_cast<const float4*>(inp + (size_t)(mbase + row) * DIM + k0 + lc4 * 4);
            As[lc4 * 4 + 0][row] = a.x; As[lc4 * 4 + 1][row] = a.y;
            As[lc4 * 4 + 2][row] = a.z; As[lc4 * 4 + 3][row] = a.w;
            float4 bv = *reinterpret_cast<const float4*>(w + (size_t)row * DIM + k0 + lc4 * 4);
            Bs[lc4 * 4 + 0][row] = bv.x; Bs[lc4 * 4 + 1][row] = bv.y;
            Bs[lc4 * 4 + 2][row] = bv.z; Bs[lc4 * 4 + 3][row] = bv.w;
        }
        __syncthreads();
#pragma unroll
        for (int k = 0; k < 16; k++) {
            float am[8], bn[8];
#pragma unroll
            for (int i = 0; i < 8; i++) am[i] = As[k][tm * 8 + i];
#pragma unroll
            for (int j = 0; j < 8; j++) bn[j] = Bs[k][tn * 8 + j];
#pragma unroll
            for (int i = 0; i < 8; i++)
#pragma unroll
                for (int j = 0; j < 8; j++) acc[i][j] = fmaf(am[i], bn[j], acc[i][j]);
        }
        __syncthreads();
    }
#pragma unroll
    for (int i = 0; i < 8; i++) {
        int m = mbase + tm * 8 + i;
        *reinterpret_cast<float4*>(outp + (size_t)m * DIM + tn * 8) =
            make_float4(acc[i][0], acc[i][1], acc[i][2], acc[i][3]);
        *reinterpret_cast<float4*>(outp + (size_t)m * DIM + tn * 8 + 4) =
            make_float4(acc[i][4], acc[i][5], acc[i][6], acc[i][7]);
    }
}

// ---------------------------------------------------------------------------
// Score: attn_raw[b,q,k] = mask ? -inf : dot(inp[b,q,:], key[b,k,:]) / sqrt(D)
// Mask is int32 (harness converts bool -> int32).
// Grid (S/128, S/128, B).
// ---------------------------------------------------------------------------
__global__ void __launch_bounds__(256) score_kernel(const float* __restrict__ inp,
                                                    const int* __restrict__ mask,
                                                    float* __restrict__ attn) {
    const int b  = blockIdx.z;
    const int qt = blockIdx.y;
    const int kt = blockIdx.x;

    const float* A  = inp   + ((size_t)b * SEQ + qt * 128) * DIM;
    const float* Bp = g_key + ((size_t)b * SEQ + kt * 128) * DIM;

    __shared__ float As[16][128];
    __shared__ float Bs[16][128];

    const int tid = threadIdx.x;
    const int tm  = tid >> 4;
    const int tn  = tid & 15;

    float acc[8][8];
#pragma unroll
    for (int i = 0; i < 8; i++)
#pragma unroll
        for (int j = 0; j < 8; j++) acc[i][j] = 0.f;

    const int lr  = tid >> 2;
    const int lc4 = tid & 3;

    for (int k0 = 0; k0 < DIM; k0 += 16) {
#pragma unroll
        for (int it = 0; it < 2; ++it) {
            int row = lr + it * 64;
            float4 a = *reinterpret_cast<const float4*>(A + (size_t)row * DIM + k0 + lc4 * 4);
            As[lc4 * 4 + 0][row] = a.x; As[lc4 * 4 + 1][row] = a.y;
            As[lc4 * 4 + 2][row] = a.z; As[lc4 * 4 + 3][row] = a.w;
            float4 bv = *reinterpret_cast<const float4*>(Bp + (size_t)row * DIM + k0 + lc4 * 4);
            Bs[lc4 * 4 + 0][row] = bv.x; Bs[lc4 * 4 + 1][row] = bv.y;
            Bs[lc4 * 4 + 2][row] = bv.z; Bs[lc4 * 4 + 3][row] = bv.w;
        }
        __syncthreads();
#pragma unroll
        for (int k = 0; k < 16; k++) {
            float am[8], bn[8];
#pragma unroll
            for (int i = 0; i < 8; i++) am[i] = As[k][tm * 8 + i];
#pragma unroll
            for (int j = 0; j < 8; j++) bn[j] = Bs[k][tn * 8 + j];
#pragma unroll
            for (int i = 0; i < 8; i++)
#pragma unroll
                for (int j = 0; j < 8; j++) acc[i][j] = fmaf(am[i], bn[j], acc[i][j]);
        }
        __syncthreads();
    }

    const float scale = 0.08838834764831845f;  // 1/sqrt(128)
#pragma unroll
    for (int i = 0; i < 8; i++) {
        size_t rowoff = ((size_t)b * SEQ + (size_t)qt * 128 + tm * 8 + i) * SEQ + kt * 128 + tn * 8;
        int4 m0 = *reinterpret_cast<const int4*>(mask + rowoff);
        int4 m1 = *reinterpret_cast<const int4*>(mask + rowoff + 4);
        float r[8];
        r[0] = m0.x ? NEG_INF : acc[i][0] * scale;
        r[1] = m0.y ? NEG_INF : acc[i][1] * scale;
        r[2] = m0.z ? NEG_INF : acc[i][2] * scale;
        r[3] = m0.w ? NEG_INF : acc[i][3] * scale;
        r[4] = m1.x ? NEG_INF : acc[i][4] * scale;
        r[5] = m1.y ? NEG_INF : acc[i][5] * scale;
        r[6] = m1.z ? NEG_INF : acc[i][6] * scale;
        r[7] = m1.w ? NEG_INF : acc[i][7] * scale;
        *reinterpret_cast<float4*>(attn + rowoff)     = make_float4(r[0], r[1], r[2], r[3]);
        *reinterpret_cast<float4*>(attn + rowoff + 4) = make_float4(r[4], r[5], r[6], r[7]);
    }
}

// ---------------------------------------------------------------------------
// Row softmax in-place: one CTA per row (4096 elems, 16 per thread in regs).
// ---------------------------------------------------------------------------
__global__ void __launch_bounds__(256) softmax_kernel(float* __restrict__ attn) {
    float* p = attn + (size_t)blockIdx.x * SEQ;
    const int tid = threadIdx.x;

    float v[16];
    float mx = NEG_INF;
#pragma unroll
    for (int i = 0; i < 16; i++) {
        v[i] = p[tid + i * 256];
        mx = fmaxf(mx, v[i]);
    }
    __shared__ float sh[8];
#pragma unroll
    for (int o = 16; o; o >>= 1) mx = fmaxf(mx, __shfl_xor_sync(0xffffffffu, mx, o));
    if ((tid & 31) == 0) sh[tid >> 5] = mx;
    __syncthreads();
    float m = sh[0];
#pragma unroll
    for (int i = 1; i < 8; i++) m = fmaxf(m, sh[i]);
    __syncthreads();

    float s = 0.f;
#pragma unroll
    for (int i = 0; i < 16; i++) {
        v[i] = expf(v[i] - m);
        s += v[i];
    }
#pragma unroll
    for (int o = 16; o; o >>= 1) s += __shfl_xor_sync(0xffffffffu, s, o);
    if ((tid & 31) == 0) sh[tid >> 5] = s;
    __syncthreads();
    float tot = 0.f;
#pragma unroll
    for (int i = 0; i < 8; i++) tot += sh[i];

    float inv = 1.f / tot;
#pragma unroll
    for (int i = 0; i < 16; i++) p[tid + i * 256] = v[i] * inv;
}

// ---------------------------------------------------------------------------
// PV: out[b,q,d] = sum_k attn[b,q,k] * val[b,k,d]
// Tile: 64(q) x 128(d) per CTA, BK=32, 256 threads, 4x8 microtile.
// Grid (S/64, B) = 256 CTAs.
// ---------------------------------------------------------------------------
__global__ void __launch_bounds__(256) pv_kernel(const float* __restrict__ attn,
                                                 float* __restrict__ out) {
    const int b     = blockIdx.y;
    const int qbase = blockIdx.x * 64;
    const float* A  = attn  + ((size_t)b * SEQ + qbase) * SEQ;
    const float* Bv = g_val + (size_t)b * SEQ * DIM;

    __shared__ float As[32][64];
    __shared__ float Bs[32][128];

    const int tid = threadIdx.x;
    const int tm  = tid >> 4;  // 0..15 -> m = tm*4
    const int tn  = tid & 15;  // 0..15 -> n = tn*8

    float acc[4][8];
#pragma unroll
    for (int i = 0; i < 4; i++)
#pragma unroll
        for (int j = 0; j < 8; j++) acc[i][j] = 0.f;

    const int ar  = tid >> 3;  // 0..31
    const int ac4 = tid & 7;   // 0..7

    for (int k0 = 0; k0 < SEQ; k0 += 32) {
#pragma unroll
        for (int it = 0; it < 2; ++it) {
            int row = ar + it * 32;
            float4 a = *reinterpret_cast<const float4*>(A + (size_t)row * SEQ + k0 + ac4 * 4);
            As[ac4 * 4 + 0][row] = a.x; As[ac4 * 4 + 1][row] = a.y;
            As[ac4 * 4 + 2][row] = a.z; As[ac4 * 4 + 3][row] = a.w;
        }
#pragma unroll
        for (int it = 0; it < 4; ++it) {
            int col4 = ac4 + it * 8;
            *reinterpret_cast<float4*>(&Bs[ar][col4 * 4]) =
                *reinterpret_cast<const float4*>(Bv + (size_t)(k0 + ar) * DIM + col4 * 4);
        }
        __syncthreads();
#pragma unroll
        for (int k = 0; k < 32; k++) {
            float am[4], bn[8];
#pragma unroll
            for (int i = 0; i < 4; i++) am[i] = As[k][tm * 4 + i];
#pragma unroll
            for (int j = 0; j < 8; j++) bn[j] = Bs[k][tn * 8 + j];
#pragma unroll
            for (int i = 0; i < 4; i++)
#pragma unroll
                for (int j = 0; j < 8; j++) acc[i][j] = fmaf(am[i], bn[j], acc[i][j]);
        }
        __syncthreads();
    }
#pragma unroll
    for (int i = 0; i < 4; i++) {
        size_t o = ((size_t)b * SEQ + qbase + tm * 4 + i) * DIM + tn * 8;
        *reinterpret_cast<float4*>(out + o)     = make_float4(acc[i][0], acc[i][1], acc[i][2], acc[i][3]);
        *reinterpret_cast<float4*>(out + o + 4) = make_float4(acc[i][4], acc[i][5], acc[i][6], acc[i][7]);
    }
}

// ---------------------------------------------------------------------------
extern "C" void kernel_launch(void* const* d_in, const int* in_sizes, int n_in,
                              void* d_out, int out_size) {
    const float* inp  = (const float*)d_in[0];
    const float* w_k  = (const float*)d_in[1];
    const float* w_v  = (const float*)d_in[2];
    const int*   mask = (const int*)d_in[3];
    float* outp = (float*)d_out;

    const size_t BSD = (size_t)BATCH * SEQ * DIM;  // 2,097,152
    const size_t BSS = (size_t)BATCH * SEQ * SEQ;  // 67,108,864

    float* attn;
    if ((size_t)out_size >= BSD + BSS) {
        attn = outp + BSD;  // tuple (out, attn) concatenated
    } else {
        void* p = nullptr;
        cudaGetSymbolAddress(&p, g_attn_fb);
        attn = (float*)p;
    }

    // 1,2: projections K = inp @ w_k^T, V = inp @ w_v^T
    proj_kernel<<<(BATCH * SEQ) / 128, 256>>>(inp, w_k, 0);
    proj_kernel<<<(BATCH * SEQ) / 128, 256>>>(inp, w_v, 1);
    // 3: masked scores -> attn buffer
    score_kernel<<<dim3(SEQ / 128, SEQ / 128, BATCH), 256>>>(inp, mask, attn);
    // 4: in-place softmax per row
    softmax_kernel<<<BATCH * SEQ, 256>>>(attn);
    // 5: out = attn @ V
    pv_kernel<<<dim3(SEQ / 64, BATCH), 256>>>(attn, outp);
}

// round 3
// speedup vs baseline: 2.4877x; 2.4877x over previous
#include <cuda_runtime.h>
#include <cuda_bf16.h>
#include <math.h>
#include <stdint.h>

#define BATCH 4
#define SEQ   4096
#define DIM   128

#define NEG_INF __int_as_float(0xff800000)

// Scratch (allocation-free: __device__ globals)
__device__ float g_key[(size_t)BATCH * SEQ * DIM];
__device__ float g_val[(size_t)BATCH * SEQ * DIM];
__device__ float g_attn_fb[(size_t)BATCH * SEQ * SEQ];

// ---------------------------------------------------------------------------
// MMA helpers
// ---------------------------------------------------------------------------
__device__ __forceinline__ uint32_t smem_u32(const void* p) {
    return (uint32_t)__cvta_generic_to_shared(p);
}

__device__ __forceinline__ void ldsm4(uint32_t& r0, uint32_t& r1, uint32_t& r2, uint32_t& r3,
                                      uint32_t addr) {
    asm volatile("ldmatrix.sync.aligned.m8n8.x4.shared.b16 {%0,%1,%2,%3},[%4];\n"
                 : "=r"(r0), "=r"(r1), "=r"(r2), "=r"(r3) : "r"(addr));
}

__device__ __forceinline__ void ldsm4t(uint32_t& r0, uint32_t& r1, uint32_t& r2, uint32_t& r3,
                                       uint32_t addr) {
    asm volatile("ldmatrix.sync.aligned.m8n8.x4.trans.shared.b16 {%0,%1,%2,%3},[%4];\n"
                 : "=r"(r0), "=r"(r1), "=r"(r2), "=r"(r3) : "r"(addr));
}

__device__ __forceinline__ void mma16816(float* c, const uint32_t* a, uint32_t b0, uint32_t b1) {
    asm volatile(
        "mma.sync.aligned.m16n8k16.row.col.f32.bf16.bf16.f32 "
        "{%0,%1,%2,%3},{%4,%5,%6,%7},{%8,%9},{%0,%1,%2,%3};\n"
        : "+f"(c[0]), "+f"(c[1]), "+f"(c[2]), "+f"(c[3])
        : "r"(a[0]), "r"(a[1]), "r"(a[2]), "r"(a[3]), "r"(b0), "r"(b1));
}

__device__ __forceinline__ uint32_t bf2pack(float x, float y) {
    __nv_bfloat162 h = __floats2bfloat162_rn(x, y);
    return *reinterpret_cast<uint32_t*>(&h);
}

// Split a float4 into hi/lo bf16x2 pairs and store (8 bytes each).
__device__ __forceinline__ void split_store(float4 f, __nv_bfloat16* hp, __nv_bfloat16* lp) {
    float h0 = __bfloat162float(__float2bfloat16(f.x));
    float h1 = __bfloat162float(__float2bfloat16(f.y));
    float h2 = __bfloat162float(__float2bfloat16(f.z));
    float h3 = __bfloat162float(__float2bfloat16(f.w));
    uint2 hi, lo;
    hi.x = bf2pack(f.x, f.y);
    hi.y = bf2pack(f.z, f.w);
    lo.x = bf2pack(f.x - h0, f.y - h1);
    lo.y = bf2pack(f.z - h2, f.w - h3);
    *reinterpret_cast<uint2*>(hp) = hi;
    *reinterpret_cast<uint2*>(lp) = lo;
}

// ---------------------------------------------------------------------------
// Projection: out[m,e] = sum_d inp[m,d] * w[e,d]  (fp32 SIMT, small)
// ---------------------------------------------------------------------------
__global__ void __launch_bounds__(256) proj_kernel(const float* __restrict__ inp,
                                                   const float* __restrict__ w,
                                                   int which) {
    float* outp = which ? g_val : g_key;
    __shared__ float As[16][128];
    __shared__ float Bs[16][128];

    const int tid   = threadIdx.x;
    const int mbase = blockIdx.x * 128;
    const int tm    = tid >> 4;
    const int tn    = tid & 15;

    float acc[8][8];
#pragma unroll
    for (int i = 0; i < 8; i++)
#pragma unroll
        for (int j = 0; j < 8; j++) acc[i][j] = 0.f;

    const int lr  = tid >> 2;
    const int lc4 = tid & 3;

    for (int k0 = 0; k0 < DIM; k0 += 16) {
#pragma unroll
        for (int it = 0; it < 2; ++it) {
            int row = lr + it * 64;
            float4 a = *reinterpret_cast<const float4*>(inp + (size_t)(mbase + row) * DIM + k0 + lc4 * 4);
            As[lc4 * 4 + 0][row] = a.x; As[lc4 * 4 + 1][row] = a.y;
            As[lc4 * 4 + 2][row] = a.z; As[lc4 * 4 + 3][row] = a.w;
            float4 bv = *reinterpret_cast<const float4*>(w + (size_t)row * DIM + k0 + lc4 * 4);
            Bs[lc4 * 4 + 0][row] = bv.x; Bs[lc4 * 4 + 1][row] = bv.y;
            Bs[lc4 * 4 + 2][row] = bv.z; Bs[lc4 * 4 + 3][row] = bv.w;
        }
        __syncthreads();
#pragma unroll
        for (int k = 0; k < 16; k++) {
            float am[8], bn[8];
#pragma unroll
            for (int i = 0; i < 8; i++) am[i] = As[k][tm * 8 + i];
#pragma unroll
            for (int j = 0; j < 8; j++) bn[j] = Bs[k][tn * 8 + j];
#pragma unroll
            for (int i = 0; i < 8; i++)
#pragma unroll
                for (int j = 0; j < 8; j++) acc[i][j] = fmaf(am[i], bn[j], acc[i][j]);
        }
        __syncthreads();
    }
#pragma unroll
    for (int i = 0; i < 8; i++) {
        int m = mbase + tm * 8 + i;
        *reinterpret_cast<float4*>(outp + (size_t)m * DIM + tn * 8) =
            make_float4(acc[i][0], acc[i][1], acc[i][2], acc[i][3]);
        *reinterpret_cast<float4*>(outp + (size_t)m * DIM + tn * 8 + 4) =
            make_float4(acc[i][4], acc[i][5], acc[i][6], acc[i][7]);
    }
}

// ---------------------------------------------------------------------------
// Score via split-bf16 tensor-core MMA.
// CTA = 128(q) x 128(k), D=128 fully resident. 8 warps, warp tile 32x64.
// attn_raw = mask ? -inf : (q . k)/sqrt(D)
// ---------------------------------------------------------------------------
#define SA 136  // padded bf16 row stride for 128-wide tiles

__global__ void __launch_bounds__(256, 1) score_mma_kernel(const float* __restrict__ inp,
                                                           const int* __restrict__ mask,
                                                           float* __restrict__ attn) {
    extern __shared__ char smraw[];
    __nv_bfloat16* Ahi = (__nv_bfloat16*)smraw;     // [128][SA]
    __nv_bfloat16* Alo = Ahi + 128 * SA;
    __nv_bfloat16* Bhi = Alo + 128 * SA;
    __nv_bfloat16* Blo = Bhi + 128 * SA;

    const int b  = blockIdx.z;
    const int qt = blockIdx.y;
    const int kt = blockIdx.x;
    const int tid = threadIdx.x;

    const float* A = inp   + ((size_t)b * SEQ + qt * 128) * DIM;
    const float* B = g_key + ((size_t)b * SEQ + kt * 128) * DIM;

    // Load + split both 128x128 fp32 tiles into hi/lo bf16 smem.
#pragma unroll
    for (int i = 0; i < 16; i++) {
        int s = tid + i * 256;          // 0..4095 float4 slots
        int row = s >> 5, c4 = (s & 31) * 4;
        float4 a = *reinterpret_cast<const float4*>(A + (size_t)row * DIM + c4);
        split_store(a, Ahi + row * SA + c4, Alo + row * SA + c4);
    }
#pragma unroll
    for (int i = 0; i < 16; i++) {
        int s = tid + i * 256;
        int row = s >> 5, c4 = (s & 31) * 4;
        float4 v = *reinterpret_cast<const float4*>(B + (size_t)row * DIM + c4);
        split_store(v, Bhi + row * SA + c4, Blo + row * SA + c4);
    }
    __syncthreads();

    const int lane = tid & 31, warp = tid >> 5;
    const int m0 = (warp >> 1) * 32;   // q offset in tile
    const int n0 = (warp & 1) * 64;    // k offset in tile

    float acc[2][8][4];
#pragma unroll
    for (int i = 0; i < 2; i++)
#pragma unroll
        for (int j = 0; j < 8; j++)
#pragma unroll
            for (int r = 0; r < 4; r++) acc[i][j][r] = 0.f;

    // ldmatrix lane-address components
    const int a_row = lane & 15;
    const int a_col = (lane >> 4) << 3;
    const int b_row = (lane & 7) + ((lane >> 4) << 3);
    const int b_col = ((lane >> 3) & 1) << 3;

#pragma unroll
    for (int ks = 0; ks < 8; ks++) {
        const int k = ks * 16;
        uint32_t ah[2][4], al[2][4];
#pragma unroll
        for (int am = 0; am < 2; am++) {
            uint32_t ad = smem_u32(Ahi + (m0 + am * 16 + a_row) * SA + k + a_col);
            ldsm4(ah[am][0], ah[am][1], ah[am][2], ah[am][3], ad);
            ad = smem_u32(Alo + (m0 + am * 16 + a_row) * SA + k + a_col);
            ldsm4(al[am][0], al[am][1], al[am][2], al[am][3], ad);
        }
        uint32_t bh[4][4], bl[4][4];
#pragma unroll
        for (int bn = 0; bn < 4; bn++) {
            uint32_t ad = smem_u32(Bhi + (n0 + bn * 16 + b_row) * SA + k + b_col);
            ldsm4(bh[bn][0], bh[bn][1], bh[bn][2], bh[bn][3], ad);
            ad = smem_u32(Blo + (n0 + bn * 16 + b_row) * SA + k + b_col);
            ldsm4(bl[bn][0], bl[bn][1], bl[bn][2], bl[bn][3], ad);
        }
#pragma unroll
        for (int am = 0; am < 2; am++)
#pragma unroll
            for (int na = 0; na < 8; na++) {
                const int g = na >> 1, o = (na & 1) * 2;
                mma16816(acc[am][na], ah[am], bh[g][o], bh[g][o + 1]);
                mma16816(acc[am][na], ah[am], bl[g][o], bl[g][o + 1]);
                mma16816(acc[am][na], al[am], bh[g][o], bh[g][o + 1]);
            }
    }

    // Epilogue: scale, mask, store fp32
    const float scale = 0.08838834764831845f;  // 1/sqrt(128)
    const int r0 = lane >> 2, c0 = (lane & 3) * 2;
#pragma unroll
    for (int am = 0; am < 2; am++)
#pragma unroll
        for (int na = 0; na < 8; na++)
#pragma unroll
            for (int h = 0; h < 2; h++) {
                int gq = qt * 128 + m0 + am * 16 + r0 + h * 8;
                int gk = kt * 128 + n0 + na * 8 + c0;
                size_t idx = ((size_t)b * SEQ + gq) * SEQ + gk;
                int2 mv = *reinterpret_cast<const int2*>(mask + idx);
                float2 o;
                o.x = mv.x ? NEG_INF : acc[am][na][h * 2 + 0] * scale;
                o.y = mv.y ? NEG_INF : acc[am][na][h * 2 + 1] * scale;
                *reinterpret_cast<float2*>(attn + idx) = o;
            }
}

// ---------------------------------------------------------------------------
// Row softmax in-place: one CTA per row.
// ---------------------------------------------------------------------------
__global__ void __launch_bounds__(256) softmax_kernel(float* __restrict__ attn) {
    float* p = attn + (size_t)blockIdx.x * SEQ;
    const int tid = threadIdx.x;

    float v[16];
    float mx = NEG_INF;
#pragma unroll
    for (int i = 0; i < 16; i++) {
        v[i] = p[tid + i * 256];
        mx = fmaxf(mx, v[i]);
    }
    __shared__ float sh[8];
#pragma unroll
    for (int o = 16; o; o >>= 1) mx = fmaxf(mx, __shfl_xor_sync(0xffffffffu, mx, o));
    if ((tid & 31) == 0) sh[tid >> 5] = mx;
    __syncthreads();
    float m = sh[0];
#pragma unroll
    for (int i = 1; i < 8; i++) m = fmaxf(m, sh[i]);
    __syncthreads();

    float s = 0.f;
#pragma unroll
    for (int i = 0; i < 16; i++) {
        v[i] = expf(v[i] - m);
        s += v[i];
    }
#pragma unroll
    for (int o = 16; o; o >>= 1) s += __shfl_xor_sync(0xffffffffu, s, o);
    if ((tid & 31) == 0) sh[tid >> 5] = s;
    __syncthreads();
    float tot = 0.f;
#pragma unroll
    for (int i = 0; i < 8; i++) tot += sh[i];

    float inv = 1.f / tot;
#pragma unroll
    for (int i = 0; i < 16; i++) p[tid + i * 256] = v[i] * inv;
}

// ---------------------------------------------------------------------------
// PV via split-bf16 tensor-core MMA.
// CTA = 128(q) x 128(d), K-loop over seq in chunks of 64, on-the-fly split.
// ---------------------------------------------------------------------------
#define SPA 72   // attn tile stride (64 + 8)
#define SPV 136  // val tile stride (128 + 8)

__global__ void __launch_bounds__(256, 1) pv_mma_kernel(const float* __restrict__ attn,
                                                        float* __restrict__ out) {
    extern __shared__ char smraw[];
    __nv_bfloat16* Ahi = (__nv_bfloat16*)smraw;      // [128][SPA]
    __nv_bfloat16* Alo = Ahi + 128 * SPA;
    __nv_bfloat16* Vhi = Alo + 128 * SPA;            // [64][SPV]
    __nv_bfloat16* Vlo = Vhi + 64 * SPV;

    const int b  = blockIdx.y;
    const int qb = blockIdx.x * 128;
    const int tid = threadIdx.x;

    const float* A = attn  + ((size_t)b * SEQ + qb) * SEQ;
    const float* V = g_val + (size_t)b * SEQ * DIM;

    const int lane = tid & 31, warp = tid >> 5;
    const int m0 = (warp >> 1) * 32;   // q
    const int n0 = (warp & 1) * 64;    // d

    float acc[2][8][4];
#pragma unroll
    for (int i = 0; i < 2; i++)
#pragma unroll
        for (int j = 0; j < 8; j++)
#pragma unroll
            for (int r = 0; r < 4; r++) acc[i][j][r] = 0.f;

    const int a_row = lane & 15;
    const int a_col = (lane >> 4) << 3;
    const int v_row = (lane & 7) + (((lane >> 3) & 1) << 3);
    const int v_col = (lane >> 4) << 3;

    for (int kc = 0; kc < SEQ / 64; kc++) {
        const int kb = kc * 64;
        // attn tile [128 q][64 k] fp32 -> hi/lo
#pragma unroll
        for (int i = 0; i < 8; i++) {
            int s = tid + i * 256;          // 0..2047 float4 slots
            int row = s >> 4, c4 = (s & 15) * 4;
            float4 a = *reinterpret_cast<const float4*>(A + (size_t)row * SEQ + kb + c4);
            split_store(a, Ahi + row * SPA + c4, Alo + row * SPA + c4);
        }
        // val tile [64 k][128 d] fp32 -> hi/lo
#pragma unroll
        for (int i = 0; i < 8; i++) {
            int s = tid + i * 256;
            int row = s >> 5, c4 = (s & 31) * 4;
            float4 v = *reinterpret_cast<const float4*>(V + (size_t)(kb + row) * DIM + c4);
            split_store(v, Vhi + row * SPV + c4, Vlo + row * SPV + c4);
        }
        __syncthreads();

#pragma unroll
        for (int ks = 0; ks < 4; ks++) {
            const int k = ks * 16;
            uint32_t ah[2][4], al[2][4];
#pragma unroll
            for (int am = 0; am < 2; am++) {
                uint32_t ad = smem_u32(Ahi + (m0 + am * 16 + a_row) * SPA + k + a_col);
                ldsm4(ah[am][0], ah[am][1], ah[am][2], ah[am][3], ad);
                ad = smem_u32(Alo + (m0 + am * 16 + a_row) * SPA + k + a_col);
                ldsm4(al[am][0], al[am][1], al[am][2], al[am][3], ad);
            }
            uint32_t bh[4][4], bl[4][4];
#pragma unroll
            for (int bn = 0; bn < 4; bn++) {
                uint32_t ad = smem_u32(Vhi + (k + v_row) * SPV + n0 + bn * 16 + v_col);
                ldsm4t(bh[bn][0], bh[bn][1], bh[bn][2], bh[bn][3], ad);
                ad = smem_u32(Vlo + (k + v_row) * SPV + n0 + bn * 16 + v_col);
                ldsm4t(bl[bn][0], bl[bn][1], bl[bn][2], bl[bn][3], ad);
            }
#pragma unroll
            for (int am = 0; am < 2; am++)
#pragma unroll
                for (int na = 0; na < 8; na++) {
                    const int g = na >> 1, o = (na & 1) * 2;
                    mma16816(acc[am][na], ah[am], bh[g][o], bh[g][o + 1]);
                    mma16816(acc[am][na], ah[am], bl[g][o], bl[g][o + 1]);
                    mma16816(acc[am][na], al[am], bh[g][o], bh[g][o + 1]);
                }
        }
        __syncthreads();
    }

    // Epilogue: store out fp32
    const int r0 = lane >> 2, c0 = (lane & 3) * 2;
#pragma unroll
    for (int am = 0; am < 2; am++)
#pragma unroll
        for (int na = 0; na < 8; na++)
#pragma unroll
            for (int h = 0; h < 2; h++) {
                int gq = qb + m0 + am * 16 + r0 + h * 8;
                int gd = n0 + na * 8 + c0;
                size_t idx = ((size_t)b * SEQ + gq) * DIM + gd;
                float2 o;
                o.x = acc[am][na][h * 2 + 0];
                o.y = acc[am][na][h * 2 + 1];
                *reinterpret_cast<float2*>(out + idx) = o;
            }
}

// ---------------------------------------------------------------------------
extern "C" void kernel_launch(void* const* d_in, const int* in_sizes, int n_in,
                              void* d_out, int out_size) {
    const float* inp  = (const float*)d_in[0];
    const float* w_k  = (const float*)d_in[1];
    const float* w_v  = (const float*)d_in[2];
    const int*   mask = (const int*)d_in[3];
    float* outp = (float*)d_out;

    const size_t BSD = (size_t)BATCH * SEQ * DIM;
    const size_t BSS = (size_t)BATCH * SEQ * SEQ;

    float* attn;
    if ((size_t)out_size >= BSD + BSS) {
        attn = outp + BSD;
    } else {
        void* p = nullptr;
        cudaGetSymbolAddress(&p, g_attn_fb);
        attn = (float*)p;
    }

    const int score_smem = 4 * 128 * SA * 2;                 // 139264
    const int pv_smem    = 2 * 128 * SPA * 2 + 2 * 64 * SPV * 2;  // 71680
    cudaFuncSetAttribute(score_mma_kernel, cudaFuncAttributeMaxDynamicSharedMemorySize, score_smem);
    cudaFuncSetAttribute(pv_mma_kernel, cudaFuncAttributeMaxDynamicSharedMemorySize, pv_smem);

    proj_kernel<<<(BATCH * SEQ) / 128, 256>>>(inp, w_k, 0);
    proj_kernel<<<(BATCH * SEQ) / 128, 256>>>(inp, w_v, 1);
    score_mma_kernel<<<dim3(SEQ / 128, SEQ / 128, BATCH), 256, score_smem>>>(inp, mask, attn);
    softmax_kernel<<<BATCH * SEQ, 256>>>(attn);
    pv_mma_kernel<<<dim3(SEQ / 128, BATCH), 256, pv_smem>>>(attn, outp);
}